// round 3
// baseline (speedup 1.0000x reference)
#include <cuda_runtime.h>

// ---------------- problem constants ----------------
#define BATCH    16384
#define INDIM    219      // 24*8 + 3 + 8 + 16
#define HID      64
#define NB       9        // 1 silu base + 8 spline bases
#define ROWS     32       // batch rows per block
#define CI       16       // input-chunk size
#define THREADS  256
#define KMAXC    (CI * NB)   // 144 k-values per full chunk
#define APAD     20          // float2 stride per k-row (padding: 4 f32x2)

// Duplicated layer-1 weights: W2[k][o] = {w, w}, k = i*9+g
// g=0 -> w_base1, g=1..8 -> coef1[...,g-1].  ~1 MB, L2-resident.
__device__ __align__(16) float2 W2[INDIM * NB * HID];

// ---------------- helpers ----------------
__device__ __forceinline__ float siluf(float x) {
    return x / (1.0f + __expf(-x));
}

__device__ __forceinline__ void ffma2(unsigned long long& acc,
                                      unsigned long long a,
                                      unsigned long long w) {
    asm("fma.rn.f32x2 %0, %1, %2, %0;" : "+l"(acc) : "l"(a), "l"(w));
}

// Uniform cubic B-spline local weights (exact closed form of the reference
// Cox-de Boor recursion on the uniform extended grid).
// knots k_j = -2.2 + 0.4*j; for x in [k_m, k_{m+1}): bases j = m-3..m.
__device__ __forceinline__ void spline_local(float x, int& m,
                                             float& n0, float& n1,
                                             float& n2, float& n3) {
    float tt = (x + 2.2f) * 2.5f;
    float mf = floorf(tt);
    m = (int)mf;
    float u = tt - mf;
    float v = 1.0f - u;
    float u2 = u * u, u3 = u2 * u;
    n0 = v * v * v * (1.0f / 6.0f);
    n1 = (3.0f * u3 - 6.0f * u2 + 4.0f) * (1.0f / 6.0f);
    n2 = (-3.0f * u3 + 3.0f * u2 + 3.0f * u + 1.0f) * (1.0f / 6.0f);
    n3 = u3 * (1.0f / 6.0f);
}

// ---------------- weight repack ----------------
__global__ void repack_kernel(const float* __restrict__ wb1,
                              const float* __restrict__ c1) {
    int idx = blockIdx.x * blockDim.x + threadIdx.x;   // over 219*64
    if (idx < INDIM * HID) {
        int i = idx / HID;
        int o = idx - i * HID;
        float w = wb1[idx];
        W2[(i * NB + 0) * HID + o] = make_float2(w, w);
#pragma unroll
        for (int g = 0; g < 8; g++) {
            float c = c1[idx * 8 + g];
            W2[(i * NB + 1 + g) * HID + o] = make_float2(c, c);
        }
    }
}

// ---------------- fused KAN forward ----------------
__global__ __launch_bounds__(THREADS, 3)
void kan_main(const float* __restrict__ hist,
              const float* __restrict__ statf,
              const float* __restrict__ timef,
              const int*   __restrict__ st_idx,
              const float* __restrict__ emb,
              const float* __restrict__ wb2,
              const float* __restrict__ c2,
              float* __restrict__ out) {
    // a2[k][rp] = {a[2*rp], a[2*rp+1]}   (row-pair packed, padded stride)
    __shared__ float2 a2[KMAXC][APAD];         // 23,040 B
    __shared__ int sidx[ROWS];
    float* af = reinterpret_cast<float*>(a2);  // af[k*2*APAD + row]

    const int t = threadIdx.x;
    const int row0 = blockIdx.x * ROWS;
    if (t < ROWS) sidx[t] = st_idx[row0 + t];

    // thread decomposition: t = rg*64 + og*4 + kq
    const int rg = t >> 6;          // 0..3   -> row-pairs rg*4 .. rg*4+3
    const int og = (t >> 2) & 15;   // 0..15  -> outputs og*4 .. og*4+3
    const int kq = t & 3;           // 0..3   -> k-slice (stride 4)
    const int arow = t & 31;        // phase-A row
    __syncthreads();

    unsigned long long acc[4][4];
#pragma unroll
    for (int p = 0; p < 4; p++)
#pragma unroll
        for (int q = 0; q < 4; q++) acc[p][q] = 0ull;

    for (int i0 = 0; i0 < INDIM; i0 += CI) {
        const int ci = min(CI, INDIM - i0);

        // ---- phase A: activations for this chunk ----
        for (int il = t >> 5; il < ci; il += 8) {
            int i  = i0 + il;
            int rb = row0 + arow;
            float x;
            if (i < 192)      x = hist[rb * 192 + i];
            else if (i < 195) x = statf[rb * 3 + (i - 192)];
            else if (i < 203) x = timef[rb * 8 + (i - 195)];
            else              x = emb[sidx[arow] * 16 + (i - 203)];

            int kb = il * NB;
            float* dst = af + (size_t)kb * (2 * APAD) + arow;
            dst[0] = siluf(x);
#pragma unroll
            for (int g = 1; g < NB; g++) dst[g * 2 * APAD] = 0.0f;

            int m; float n0, n1, n2, n3;
            spline_local(x, m, n0, n1, n2, n3);
            if (m >= 0 && m <= 10) {
                int j0 = m - 3;
                if (m >= 3)           dst[(1 + j0)     * 2 * APAD] = n0;
                if (m >= 2 && m <= 9) dst[(1 + j0 + 1) * 2 * APAD] = n1;
                if (m >= 1 && m <= 8) dst[(1 + j0 + 2) * 2 * APAD] = n2;
                if (m <= 7)           dst[(1 + m)      * 2 * APAD] = n3;
            }
        }
        __syncthreads();

        // ---- phase B: register-tiled GEMM slice, 4-way k-split ----
        const float2* wbase = W2 + (size_t)i0 * NB * HID + og * 4;
        const int kmax = ci * NB;
#pragma unroll 2
        for (int k = kq; k < kmax; k += 4) {
            const ulonglong2* ap =
                reinterpret_cast<const ulonglong2*>(&a2[k][rg * 4]);
            ulonglong2 alo = ap[0];              // row-pairs p=0,1
            ulonglong2 ahi = ap[1];              // row-pairs p=2,3
            const ulonglong2* wp =
                reinterpret_cast<const ulonglong2*>(wbase + (size_t)k * HID);
            ulonglong2 w0 = wp[0];               // outputs q=0,1 (dup)
            ulonglong2 w1 = wp[1];               // outputs q=2,3 (dup)

            ffma2(acc[0][0], alo.x, w0.x);
            ffma2(acc[0][1], alo.x, w0.y);
            ffma2(acc[0][2], alo.x, w1.x);
            ffma2(acc[0][3], alo.x, w1.y);
            ffma2(acc[1][0], alo.y, w0.x);
            ffma2(acc[1][1], alo.y, w0.y);
            ffma2(acc[1][2], alo.y, w1.x);
            ffma2(acc[1][3], alo.y, w1.y);
            ffma2(acc[2][0], ahi.x, w0.x);
            ffma2(acc[2][1], ahi.x, w0.y);
            ffma2(acc[2][2], ahi.x, w1.x);
            ffma2(acc[2][3], ahi.x, w1.y);
            ffma2(acc[3][0], ahi.y, w0.x);
            ffma2(acc[3][1], ahi.y, w0.y);
            ffma2(acc[3][2], ahi.y, w1.x);
            ffma2(acc[3][3], ahi.y, w1.y);
        }
        __syncthreads();
    }

    // ---- reduce the 4 k-slices (lane-adjacent partners) ----
    float* hf = reinterpret_cast<float*>(a2);   // reuse as h[32][64]
#pragma unroll
    for (int p = 0; p < 4; p++)
#pragma unroll
        for (int q = 0; q < 4; q++) {
            float2 v = *reinterpret_cast<float2*>(&acc[p][q]);
            v.x += __shfl_xor_sync(0xffffffffu, v.x, 1);
            v.y += __shfl_xor_sync(0xffffffffu, v.y, 1);
            v.x += __shfl_xor_sync(0xffffffffu, v.x, 2);
            v.y += __shfl_xor_sync(0xffffffffu, v.y, 2);
            if (kq == 0) {
                int rp = rg * 4 + p;
                int o  = og * 4 + q;
                hf[(2 * rp)     * HID + o] = v.x;
                hf[(2 * rp + 1) * HID + o] = v.y;
            }
        }
    __syncthreads();

    // ---- layer 2: 8 threads per row, each covers 8 hidden units ----
    const int row = t >> 3;
    const int sub = t & 7;
    float accum = 0.0f;
#pragma unroll
    for (int kk = 0; kk < 8; kk++) {
        int o = sub + kk * 8;
        float xv = hf[row * HID + o];
        float v = siluf(xv) * __ldg(&wb2[o]);

        int m; float n0, n1, n2, n3;
        spline_local(xv, m, n0, n1, n2, n3);
        if (m >= 0 && m <= 10) {
            int j0 = m - 3;
#pragma unroll
            for (int j = 0; j < 8; j++) {
                int d = j - j0;
                float nb = (d == 0) ? n0 : (d == 1) ? n1 : (d == 2) ? n2
                         : (d == 3) ? n3 : 0.0f;
                v += nb * __ldg(&c2[o * 8 + j]);
            }
        }
        accum += v;
    }
    accum += __shfl_xor_sync(0xffffffffu, accum, 4);
    accum += __shfl_xor_sync(0xffffffffu, accum, 2);
    accum += __shfl_xor_sync(0xffffffffu, accum, 1);
    if (sub == 0) out[row0 + row] = accum;
}

// ---------------- launch ----------------
extern "C" void kernel_launch(void* const* d_in, const int* in_sizes, int n_in,
                              void* d_out, int out_size) {
    const float* hist  = (const float*)d_in[0];
    const float* statf = (const float*)d_in[1];
    const float* timef = (const float*)d_in[2];
    const int*   sti   = (const int*)  d_in[3];
    const float* emb   = (const float*)d_in[4];
    const float* wb1   = (const float*)d_in[5];
    const float* c1    = (const float*)d_in[6];
    const float* wb2   = (const float*)d_in[7];
    const float* c2    = (const float*)d_in[8];
    float* out = (float*)d_out;

    repack_kernel<<<(INDIM * HID + 255) / 256, 256>>>(wb1, c1);
    kan_main<<<BATCH / ROWS, THREADS>>>(hist, statf, timef, sti, emb, wb2, c2, out);
}

// round 5
// speedup vs baseline: 2.0213x; 2.0213x over previous
#include <cuda_runtime.h>

// ---------------- problem constants ----------------
#define BATCH    16384
#define INDIM    219
#define HID      64
#define NB       9          // silu base + 8 spline bases
#define ROWS     64         // batch rows per block
#define CI       4          // inputs per chunk
#define KC       (CI * NB)  // 36 k-rows per chunk
#define NCHUNK   55         // ceil(219/4)
#define THREADS  128

// Duplicated packed layer-1 weights: W2g[k][o] = {w,w}, k = i*9+g (padded to 1980 k-rows)
__device__ __align__(16) float2 W2g[1980 * HID];   // ~1.01 MB, L2-resident

// ---------------- helpers ----------------
__device__ __forceinline__ float siluf(float x) {
    return x / (1.0f + __expf(-x));
}
__device__ __forceinline__ void ffma2(unsigned long long& acc,
                                      unsigned long long a,
                                      unsigned long long w) {
    asm("fma.rn.f32x2 %0, %1, %2, %0;" : "+l"(acc) : "l"(a), "l"(w));
}
__device__ __forceinline__ void cp16(unsigned int dst, const void* src) {
    asm volatile("cp.async.cg.shared.global [%0], [%1], 16;" :: "r"(dst), "l"(src));
}
__device__ __forceinline__ void cp_commit() {
    asm volatile("cp.async.commit_group;");
}
__device__ __forceinline__ void cp_wait1() {
    asm volatile("cp.async.wait_group 1;");
}

// Uniform cubic B-spline local weights (exact closed form of the reference
// Cox-de Boor recursion on the uniform extended grid; knots -2.2 + 0.4*j).
__device__ __forceinline__ void spline_local(float x, int& m,
                                             float& n0, float& n1,
                                             float& n2, float& n3) {
    float tt = (x + 2.2f) * 2.5f;
    float mf = floorf(tt);
    m = (int)mf;
    float u = tt - mf;
    float v = 1.0f - u;
    float u2 = u * u, u3 = u2 * u;
    n0 = v * v * v * (1.0f / 6.0f);
    n1 = (3.0f * u3 - 6.0f * u2 + 4.0f) * (1.0f / 6.0f);
    n2 = (-3.0f * u3 + 3.0f * u2 + 3.0f * u + 1.0f) * (1.0f / 6.0f);
    n3 = u3 * (1.0f / 6.0f);
}

// ---------------- weight repack (dup into f32x2) ----------------
__global__ void repack_kernel(const float* __restrict__ wb1,
                              const float* __restrict__ c1) {
    int idx = blockIdx.x * blockDim.x + threadIdx.x;   // over 219*64
    if (idx < INDIM * HID) {
        int i = idx / HID;
        int o = idx - i * HID;
        float w = wb1[idx];
        W2g[(i * NB + 0) * HID + o] = make_float2(w, w);
#pragma unroll
        for (int g = 0; g < 8; g++) {
            float c = c1[idx * 8 + g];
            W2g[(i * NB + 1 + g) * HID + o] = make_float2(c, c);
        }
    }
}

// fetch one input feature
__device__ __forceinline__ float fetch_x(int i, int rb,
                                         const float* __restrict__ hist,
                                         const float* __restrict__ statf,
                                         const float* __restrict__ timef,
                                         const float* __restrict__ emb,
                                         int sid) {
    if (i < 192)  return hist[rb * 192 + i];
    if (i < 195)  return statf[rb * 3 + (i - 192)];
    if (i < 203)  return timef[rb * 8 + (i - 195)];
    return emb[sid * 16 + (i - 203)];
}

// ---------------- fused KAN forward ----------------
__global__ __launch_bounds__(THREADS)
void kan_main(const float* __restrict__ hist,
              const float* __restrict__ statf,
              const float* __restrict__ timef,
              const int*   __restrict__ st_idx,
              const float* __restrict__ emb,
              const float* __restrict__ wb2,
              const float* __restrict__ c2,
              float* __restrict__ out) {
    __shared__ float  a_s[KC * ROWS];         // 9216 B, a[k][row]
    __shared__ float2 w_s[2][KC * HID];       // 2 x 18432 B, w[k][o] dup
    __shared__ int sidx[ROWS];

    const int t = threadIdx.x;
    const int row0 = blockIdx.x * ROWS;
    if (t < ROWS) sidx[t] = st_idx[row0 + t];

    const int lane = t & 31;
    const int wrp  = t >> 5;
    const int og   = lane & 7;                 // out-group
    const int rg   = lane >> 3;                // row-group within warp
    const int rowbase = (wrp * 4 + rg) * 4;    // 4 consecutive rows

    // ---- prologue: commit W chunks 0,1; load+build a(0) ----
    {
        unsigned int d0 = (unsigned int)__cvta_generic_to_shared(&w_s[0][0]);
        const char* s0 = (const char*)W2g;
#pragma unroll
        for (int n = 0; n < 9; n++)
            cp16(d0 + (t + n * 128) * 16, s0 + (t + n * 128) * 16);
        cp_commit();
        unsigned int d1 = (unsigned int)__cvta_generic_to_shared(&w_s[1][0]);
        const char* s1 = (const char*)(W2g + KC * HID);
#pragma unroll
        for (int n = 0; n < 9; n++)
            cp16(d1 + (t + n * 128) * 16, s1 + (t + n * 128) * 16);
        cp_commit();
    }
    __syncthreads();   // sidx visible

    // build a(0)
#pragma unroll
    for (int it = t; it < ROWS * CI; it += THREADS) {
        int il = it >> 6, row = it & 63;
        float x = fetch_x(il, row0 + row, hist, statf, timef, emb, sidx[row]);
        float* dst = &a_s[il * NB * ROWS + row];
        dst[0] = siluf(x);
#pragma unroll
        for (int g = 1; g < NB; g++) dst[g * ROWS] = 0.0f;
        int m; float n0, n1, n2, n3;
        spline_local(x, m, n0, n1, n2, n3);
        if (m >= 0 && m <= 10) {
            int j0 = m - 3;
            if (m >= 3)           dst[(1 + j0)     * ROWS] = n0;
            if (m >= 2 && m <= 9) dst[(1 + j0 + 1) * ROWS] = n1;
            if (m >= 1 && m <= 8) dst[(1 + j0 + 2) * ROWS] = n2;
            if (m <= 7)           dst[(1 + m)      * ROWS] = n3;
        }
    }

    unsigned long long acc[2][8];
#pragma unroll
    for (int p = 0; p < 2; p++)
#pragma unroll
        for (int q = 0; q < 8; q++) acc[p][q] = 0ull;

    for (int c = 0; c < NCHUNK; c++) {
        const int ci = (c == NCHUNK - 1) ? (INDIM - c * CI) : CI;
        cp_wait1();          // W chunk c resident
        __syncthreads();     // a(c) stores + W visible to all

        // prefetch x for chunk c+1
        float xn[2]; int has[2] = {0, 0};
        if (c + 1 < NCHUNK) {
            int cin = (c + 1 == NCHUNK - 1) ? (INDIM - (c + 1) * CI) : CI;
#pragma unroll
            for (int s = 0; s < 2; s++) {
                int it = t + s * THREADS;
                if (it < ROWS * cin) {
                    int il = it >> 6, row = it & 63;
                    xn[s] = fetch_x((c + 1) * CI + il, row0 + row,
                                    hist, statf, timef, emb, sidx[row]);
                    has[s] = 1;
                }
            }
        }

        // ---- phase B: SMEM-only register-tiled GEMM slice ----
        const float2* wb = w_s[c & 1];
        const int rmax = ci * NB;
#pragma unroll 3
        for (int k = 0; k < rmax; k++) {
            ulonglong2 a = *reinterpret_cast<const ulonglong2*>(
                &a_s[k * ROWS + rowbase]);
#pragma unroll
            for (int j = 0; j < 4; j++) {
                ulonglong2 w = *reinterpret_cast<const ulonglong2*>(
                    &wb[k * HID + j * 16 + og * 2]);
                ffma2(acc[0][j * 2],     a.x, w.x);
                ffma2(acc[0][j * 2 + 1], a.x, w.y);
                ffma2(acc[1][j * 2],     a.y, w.x);
                ffma2(acc[1][j * 2 + 1], a.y, w.y);
            }
        }
        __syncthreads();     // phase B done before a_s / w_s[c&1] overwrite

        // build a(c+1)
        if (c + 1 < NCHUNK) {
#pragma unroll
            for (int s = 0; s < 2; s++) {
                if (has[s]) {
                    int it = t + s * THREADS;
                    int il = it >> 6, row = it & 63;
                    float x = xn[s];
                    float* dst = &a_s[il * NB * ROWS + row];
                    dst[0] = siluf(x);
#pragma unroll
                    for (int g = 1; g < NB; g++) dst[g * ROWS] = 0.0f;
                    int m; float n0, n1, n2, n3;
                    spline_local(x, m, n0, n1, n2, n3);
                    if (m >= 0 && m <= 10) {
                        int j0 = m - 3;
                        if (m >= 3)           dst[(1 + j0)     * ROWS] = n0;
                        if (m >= 2 && m <= 9) dst[(1 + j0 + 1) * ROWS] = n1;
                        if (m >= 1 && m <= 8) dst[(1 + j0 + 2) * ROWS] = n2;
                        if (m <= 7)           dst[(1 + m)      * ROWS] = n3;
                    }
                }
            }
        }

        // commit W chunk c+2 into buffer (c&1); empty group keeps counts aligned
        if (c + 2 < NCHUNK) {
            unsigned int d = (unsigned int)__cvta_generic_to_shared(&w_s[c & 1][0]);
            const char* s = (const char*)(W2g + (size_t)(c + 2) * KC * HID);
#pragma unroll
            for (int n = 0; n < 9; n++)
                cp16(d + (t + n * 128) * 16, s + (t + n * 128) * 16);
        }
        cp_commit();
    }

    // ---- hand off h through shared (reuse w_s as h[64][64]) ----
    __syncthreads();
    float* h = reinterpret_cast<float*>(w_s);
#pragma unroll
    for (int p = 0; p < 2; p++)
#pragma unroll
        for (int j = 0; j < 4; j++)
#pragma unroll
            for (int e = 0; e < 2; e++) {
                int o = j * 16 + og * 2 + e;
                float2 v = *reinterpret_cast<float2*>(&acc[p][j * 2 + e]);
                h[(rowbase + 2 * p)     * HID + o] = v.x;
                h[(rowbase + 2 * p + 1) * HID + o] = v.y;
            }
    __syncthreads();

    // ---- layer 2: 2 threads per row, 32 hidden units each ----
    const int row = t >> 1;
    const int sub = t & 1;
    float accum = 0.0f;
#pragma unroll
    for (int kk = 0; kk < 32; kk++) {
        int o = sub + kk * 2;
        float xv = h[row * HID + o];
        float v = siluf(xv) * __ldg(&wb2[o]);
        int m; float n0, n1, n2, n3;
        spline_local(xv, m, n0, n1, n2, n3);
        if (m >= 0 && m <= 10) {
            int j0 = m - 3;
#pragma unroll
            for (int j = 0; j < 8; j++) {
                int d = j - j0;
                float nb = (d == 0) ? n0 : (d == 1) ? n1 : (d == 2) ? n2
                         : (d == 3) ? n3 : 0.0f;
                v += nb * __ldg(&c2[o * 8 + j]);
            }
        }
        accum += v;
    }
    accum += __shfl_xor_sync(0xffffffffu, accum, 1);
    if (sub == 0) out[row0 + row] = accum;
}

// ---------------- launch ----------------
extern "C" void kernel_launch(void* const* d_in, const int* in_sizes, int n_in,
                              void* d_out, int out_size) {
    const float* hist  = (const float*)d_in[0];
    const float* statf = (const float*)d_in[1];
    const float* timef = (const float*)d_in[2];
    const int*   sti   = (const int*)  d_in[3];
    const float* emb   = (const float*)d_in[4];
    const float* wb1   = (const float*)d_in[5];
    const float* c1    = (const float*)d_in[6];
    const float* wb2   = (const float*)d_in[7];
    const float* c2    = (const float*)d_in[8];
    float* out = (float*)d_out;

    repack_kernel<<<(INDIM * HID + 255) / 256, 256>>>(wb1, c1);
    kan_main<<<BATCH / ROWS, THREADS>>>(hist, statf, timef, sti, emb, wb2, c2, out);
}

// round 6
// speedup vs baseline: 2.5389x; 1.2561x over previous
#include <cuda_runtime.h>

// ---------------- problem constants ----------------
#define BATCH    16384
#define INDIM    219
#define HID      64
#define NB       9          // silu base + 8 spline bases
#define ROWS     64         // batch rows per block
#define CI       4          // inputs per chunk
#define KC       (CI * NB)  // 36 k-rows per chunk
#define NCHUNK   55
#define THREADS  256
#define KPAD     1980       // padded k rows (55*36)

// Scalar packed layer-1 weights: Wg[k][o], k = i*9+g (zero-padded tail)
__device__ __align__(16) float Wg[KPAD * HID];   // ~507 KB, L2-resident

// ---------------- helpers ----------------
__device__ __forceinline__ float siluf(float x) {
    return x / (1.0f + __expf(-x));
}
__device__ __forceinline__ void ffma2(unsigned long long& acc,
                                      unsigned long long a,
                                      unsigned long long w) {
    asm("fma.rn.f32x2 %0, %1, %2, %0;" : "+l"(acc) : "l"(a), "l"(w));
}
__device__ __forceinline__ void cp16(unsigned int dst, const void* src) {
    asm volatile("cp.async.cg.shared.global [%0], [%1], 16;" :: "r"(dst), "l"(src));
}
__device__ __forceinline__ void cp_commit() {
    asm volatile("cp.async.commit_group;");
}
__device__ __forceinline__ void cp_wait1() {
    asm volatile("cp.async.wait_group 1;");
}

// Uniform cubic B-spline local weights (exact closed form of the reference
// Cox-de Boor recursion on the uniform extended grid; knots -2.2 + 0.4*j).
__device__ __forceinline__ void spline_local(float x, int& m,
                                             float& n0, float& n1,
                                             float& n2, float& n3) {
    float tt = (x + 2.2f) * 2.5f;
    float mf = floorf(tt);
    m = (int)mf;
    float u = tt - mf;
    float v = 1.0f - u;
    float u2 = u * u, u3 = u2 * u;
    n0 = v * v * v * (1.0f / 6.0f);
    n1 = (3.0f * u3 - 6.0f * u2 + 4.0f) * (1.0f / 6.0f);
    n2 = (-3.0f * u3 + 3.0f * u2 + 3.0f * u + 1.0f) * (1.0f / 6.0f);
    n3 = u3 * (1.0f / 6.0f);
}

// ---------------- weight repack (scalar) ----------------
__global__ void repack_kernel(const float* __restrict__ wb1,
                              const float* __restrict__ c1) {
    int idx = blockIdx.x * blockDim.x + threadIdx.x;   // over 219*64
    if (idx < INDIM * HID) {
        int i = idx / HID;
        int o = idx - i * HID;
        Wg[(i * NB + 0) * HID + o] = wb1[idx];
#pragma unroll
        for (int g = 0; g < 8; g++)
            Wg[(i * NB + 1 + g) * HID + o] = c1[idx * 8 + g];
    }
}

// fetch one input feature
__device__ __forceinline__ float fetch_x(int i, int rb,
                                         const float* __restrict__ hist,
                                         const float* __restrict__ statf,
                                         const float* __restrict__ timef,
                                         const float* __restrict__ emb,
                                         int sid) {
    if (i < 192)  return hist[rb * 192 + i];
    if (i < 195)  return statf[rb * 3 + (i - 192)];
    if (i < 203)  return timef[rb * 8 + (i - 195)];
    return emb[sid * 16 + (i - 203)];
}

// build one (input, row) activation column, duplicated for f32x2
__device__ __forceinline__ void build_act(float x, float2* a2base, int il, int row) {
    float2* dst = a2base + (size_t)(il * NB) * ROWS + row;   // stride ROWS float2
    float s = siluf(x);
    dst[0] = make_float2(s, s);
#pragma unroll
    for (int g = 1; g < NB; g++) dst[g * ROWS] = make_float2(0.0f, 0.0f);
    int m; float n0, n1, n2, n3;
    spline_local(x, m, n0, n1, n2, n3);
    if (m >= 0 && m <= 10) {
        int j0 = m - 3;
        if (m >= 3)           dst[(1 + j0)     * ROWS] = make_float2(n0, n0);
        if (m >= 2 && m <= 9) dst[(1 + j0 + 1) * ROWS] = make_float2(n1, n1);
        if (m >= 1 && m <= 8) dst[(1 + j0 + 2) * ROWS] = make_float2(n2, n2);
        if (m <= 7)           dst[(1 + m)      * ROWS] = make_float2(n3, n3);
    }
}

// ---------------- fused KAN forward ----------------
__global__ __launch_bounds__(THREADS)
void kan_main(const float* __restrict__ hist,
              const float* __restrict__ statf,
              const float* __restrict__ timef,
              const int*   __restrict__ st_idx,
              const float* __restrict__ emb,
              const float* __restrict__ wb2,
              const float* __restrict__ c2,
              float* __restrict__ out) {
    __shared__ float2 a2[KC][ROWS];        // duplicated activations, 18,432 B
    __shared__ float  w_s[2][KC * HID];    // scalar weights, 2 x 9,216 B
    __shared__ int sidx[ROWS];

    const int t = threadIdx.x;
    const int row0 = blockIdx.x * ROWS;
    if (t < ROWS) sidx[t] = st_idx[row0 + t];

    // t = kg*64 + rg*8 + og
    const int kg  = t >> 6;          // k-slice 0..3 (stride 4)
    const int og  = t & 7;           // outs og*8 .. og*8+7
    const int rg8 = ((t >> 3) & 7) * 8;  // rows rg8 .. rg8+7

    // ---- prologue: commit W chunks 0,1 ----
    {
        unsigned int d0 = (unsigned int)__cvta_generic_to_shared(&w_s[0][0]);
        const char* s0 = (const char*)Wg;
#pragma unroll
        for (int n = 0; n < 3; n++) {
            int idx = t + n * THREADS;
            if (idx < 576) cp16(d0 + idx * 16, s0 + idx * 16);
        }
        cp_commit();
        unsigned int d1 = (unsigned int)__cvta_generic_to_shared(&w_s[1][0]);
        const char* s1 = (const char*)(Wg + KC * HID);
#pragma unroll
        for (int n = 0; n < 3; n++) {
            int idx = t + n * THREADS;
            if (idx < 576) cp16(d1 + idx * 16, s1 + idx * 16);
        }
        cp_commit();
    }
    __syncthreads();   // sidx visible

    // build a(0): one (input,row) pair per thread (ROWS*CI == THREADS)
    {
        int il = t >> 6, row = t & 63;
        float x = fetch_x(il, row0 + row, hist, statf, timef, emb, sidx[row]);
        build_act(x, &a2[0][0], il, row);
    }

    unsigned long long acc[8][4];
#pragma unroll
    for (int r = 0; r < 8; r++)
#pragma unroll
        for (int p = 0; p < 4; p++) acc[r][p] = 0ull;

    for (int c = 0; c < NCHUNK; c++) {
        const int ci = (c == NCHUNK - 1) ? (INDIM - c * CI) : CI;
        cp_wait1();          // W chunk c resident
        __syncthreads();     // a(c) stores + W visible

        // prefetch x for chunk c+1
        float xn = 0.0f; int has = 0;
        if (c + 1 < NCHUNK) {
            int cin = (c + 1 == NCHUNK - 1) ? (INDIM - (c + 1) * CI) : CI;
            if (t < ROWS * cin) {
                int il = t >> 6, row = t & 63;
                xn = fetch_x((c + 1) * CI + il, row0 + row,
                             hist, statf, timef, emb, sidx[row]);
                has = 1;
            }
        }

        // ---- phase B: SMEM-only, dup-a / scalar-w, 4-way k-split ----
        const float* wb = w_s[c & 1];
        const int kmax = ci * NB;
#pragma unroll 2
        for (int k = kg; k < kmax; k += 4) {
            const ulonglong2* ap =
                reinterpret_cast<const ulonglong2*>(&a2[k][rg8]);
            ulonglong2 a01 = ap[0];
            ulonglong2 a23 = ap[1];
            ulonglong2 a45 = ap[2];
            ulonglong2 a67 = ap[3];
            const ulonglong2* wp =
                reinterpret_cast<const ulonglong2*>(&wb[k * HID + og * 8]);
            ulonglong2 wA = wp[0];   // out pairs (0,1),(2,3)
            ulonglong2 wB = wp[1];   // out pairs (4,5),(6,7)

            ffma2(acc[0][0], a01.x, wA.x); ffma2(acc[0][1], a01.x, wA.y);
            ffma2(acc[0][2], a01.x, wB.x); ffma2(acc[0][3], a01.x, wB.y);
            ffma2(acc[1][0], a01.y, wA.x); ffma2(acc[1][1], a01.y, wA.y);
            ffma2(acc[1][2], a01.y, wB.x); ffma2(acc[1][3], a01.y, wB.y);
            ffma2(acc[2][0], a23.x, wA.x); ffma2(acc[2][1], a23.x, wA.y);
            ffma2(acc[2][2], a23.x, wB.x); ffma2(acc[2][3], a23.x, wB.y);
            ffma2(acc[3][0], a23.y, wA.x); ffma2(acc[3][1], a23.y, wA.y);
            ffma2(acc[3][2], a23.y, wB.x); ffma2(acc[3][3], a23.y, wB.y);
            ffma2(acc[4][0], a45.x, wA.x); ffma2(acc[4][1], a45.x, wA.y);
            ffma2(acc[4][2], a45.x, wB.x); ffma2(acc[4][3], a45.x, wB.y);
            ffma2(acc[5][0], a45.y, wA.x); ffma2(acc[5][1], a45.y, wA.y);
            ffma2(acc[5][2], a45.y, wB.x); ffma2(acc[5][3], a45.y, wB.y);
            ffma2(acc[6][0], a67.x, wA.x); ffma2(acc[6][1], a67.x, wA.y);
            ffma2(acc[6][2], a67.x, wB.x); ffma2(acc[6][3], a67.x, wB.y);
            ffma2(acc[7][0], a67.y, wA.x); ffma2(acc[7][1], a67.y, wA.y);
            ffma2(acc[7][2], a67.y, wB.x); ffma2(acc[7][3], a67.y, wB.y);
        }
        __syncthreads();     // phase B done before a2 / w_s[c&1] overwrite

        // build a(c+1)
        if (has) {
            int il = t >> 6, row = t & 63;
            build_act(xn, &a2[0][0], il, row);
        }

        // commit W chunk c+2 (or empty group to keep counts aligned)
        if (c + 2 < NCHUNK) {
            unsigned int d = (unsigned int)__cvta_generic_to_shared(&w_s[c & 1][0]);
            const char* s = (const char*)(Wg + (size_t)(c + 2) * KC * HID);
#pragma unroll
            for (int n = 0; n < 3; n++) {
                int idx = t + n * THREADS;
                if (idx < 576) cp16(d + idx * 16, s + idx * 16);
            }
        }
        cp_commit();
    }

    // ---- reduce the 4 k-slices into h (reuse a2 as h[64][64]) ----
    __syncthreads();
    float* h = reinterpret_cast<float*>(a2);
#pragma unroll
    for (int rnd = 0; rnd < 4; rnd++) {
        if (kg == rnd) {
#pragma unroll
            for (int r = 0; r < 8; r++)
#pragma unroll
                for (int p = 0; p < 4; p++) {
                    float2 v = *reinterpret_cast<float2*>(&acc[r][p]);
                    int row = rg8 + r;
                    int o = og * 8 + p * 2;
                    if (rnd == 0) {
                        h[row * HID + o]     = v.x;
                        h[row * HID + o + 1] = v.y;
                    } else {
                        h[row * HID + o]     += v.x;
                        h[row * HID + o + 1] += v.y;
                    }
                }
        }
        __syncthreads();
    }

    // ---- layer 2: 4 threads per row, 16 hidden units each ----
    const int row = t >> 2;
    const int sub = t & 3;
    float accum = 0.0f;
#pragma unroll
    for (int kk = 0; kk < 16; kk++) {
        int o = sub + kk * 4;
        float xv = h[row * HID + o];
        float v = siluf(xv) * __ldg(&wb2[o]);
        int m; float n0, n1, n2, n3;
        spline_local(xv, m, n0, n1, n2, n3);
        if (m >= 0 && m <= 10) {
            int j0 = m - 3;
#pragma unroll
            for (int j = 0; j < 8; j++) {
                int d = j - j0;
                float nb = (d == 0) ? n0 : (d == 1) ? n1 : (d == 2) ? n2
                         : (d == 3) ? n3 : 0.0f;
                v += nb * __ldg(&c2[o * 8 + j]);
            }
        }
        accum += v;
    }
    accum += __shfl_xor_sync(0xffffffffu, accum, 1);
    accum += __shfl_xor_sync(0xffffffffu, accum, 2);
    if (sub == 0) out[row0 + row] = accum;
}

// ---------------- launch ----------------
extern "C" void kernel_launch(void* const* d_in, const int* in_sizes, int n_in,
                              void* d_out, int out_size) {
    const float* hist  = (const float*)d_in[0];
    const float* statf = (const float*)d_in[1];
    const float* timef = (const float*)d_in[2];
    const int*   sti   = (const int*)  d_in[3];
    const float* emb   = (const float*)d_in[4];
    const float* wb1   = (const float*)d_in[5];
    const float* c1    = (const float*)d_in[6];
    const float* wb2   = (const float*)d_in[7];
    const float* c2    = (const float*)d_in[8];
    float* out = (float*)d_out;

    repack_kernel<<<(INDIM * HID + 255) / 256, 256>>>(wb1, c1);
    kan_main<<<BATCH / ROWS, THREADS>>>(hist, statf, timef, sti, emb, wb2, c2, out);
}

// round 8
// speedup vs baseline: 4.8728x; 1.9192x over previous
#include <cuda_runtime.h>
#include <cuda_bf16.h>
#include <cstdint>

// ---------------- problem constants ----------------
#define BATCH   16384
#define INDIM   219
#define HID     64
#define NCH     14          // K chunks
#define CK      144         // K per chunk = 16 bases + 16*8 splines
#define KTOT    2016
#define MROWS   64
#define THREADS 128
#define AS      152         // A smem row stride (elems) -> 304 B
#define WS      72          // W smem row stride (elems) -> 144 B
#define WCHUNK_HALF 20736   // 144 k * 144 B
#define WCHUNK      41472

// Pre-split, pre-padded W chunk images: [chunk][hi 20736 | lo 20736]
__device__ __align__(16) unsigned char Wimg[NCH * WCHUNK];

// ---------------- smem layout ----------------
#define SM_SIDX 0
#define SM_A    256                       // Ah: 64*304 = 19456
#define SM_AL   (SM_A + MROWS * AS * 2)   // Al: 19456
#define SM_W    (SM_AL + MROWS * AS * 2)  // 41472
#define SMEM_TOTAL (SM_W + WCHUNK)

// ---------------- PTX helpers ----------------
__device__ __forceinline__ uint32_t smem_u32(const void* p) {
    uint32_t a;
    asm("{ .reg .u64 t; cvta.to.shared.u64 t, %1; cvt.u32.u64 %0, t; }"
        : "=r"(a) : "l"(p));
    return a;
}
__device__ __forceinline__ void ldsm4(uint32_t* d, uint32_t addr) {
    asm volatile("ldmatrix.sync.aligned.m8n8.x4.shared.b16 {%0,%1,%2,%3}, [%4];"
                 : "=r"(d[0]), "=r"(d[1]), "=r"(d[2]), "=r"(d[3]) : "r"(addr));
}
__device__ __forceinline__ void ldsm4t(uint32_t* d, uint32_t addr) {
    asm volatile("ldmatrix.sync.aligned.m8n8.x4.trans.shared.b16 {%0,%1,%2,%3}, [%4];"
                 : "=r"(d[0]), "=r"(d[1]), "=r"(d[2]), "=r"(d[3]) : "r"(addr));
}
__device__ __forceinline__ void mma16816(float* c, const uint32_t* a,
                                         uint32_t b0, uint32_t b1) {
    asm volatile("mma.sync.aligned.m16n8k16.row.col.f32.bf16.bf16.f32 "
                 "{%0,%1,%2,%3}, {%4,%5,%6,%7}, {%8,%9}, {%0,%1,%2,%3};"
                 : "+f"(c[0]), "+f"(c[1]), "+f"(c[2]), "+f"(c[3])
                 : "r"(a[0]), "r"(a[1]), "r"(a[2]), "r"(a[3]), "r"(b0), "r"(b1));
}
__device__ __forceinline__ void cp16(uint32_t dst, const void* src) {
    asm volatile("cp.async.cg.shared.global [%0], [%1], 16;" :: "r"(dst), "l"(src));
}

// ---------------- math helpers ----------------
__device__ __forceinline__ float siluf(float x) { return x / (1.0f + __expf(-x)); }

// Exact closed form of the reference Cox-de Boor cubic recursion on the
// uniform extended grid (knots -2.2 + 0.4*j).
__device__ __forceinline__ void spline_local(float x, int& m, float& n0, float& n1,
                                             float& n2, float& n3) {
    float tt = (x + 2.2f) * 2.5f;
    float mf = floorf(tt);
    m = (int)mf;
    float u = tt - mf, v = 1.0f - u;
    float u2 = u * u, u3 = u2 * u;
    n0 = v * v * v * (1.0f / 6.0f);
    n1 = (3.0f * u3 - 6.0f * u2 + 4.0f) * (1.0f / 6.0f);
    n2 = (-3.0f * u3 + 3.0f * u2 + 3.0f * u + 1.0f) * (1.0f / 6.0f);
    n3 = u3 * (1.0f / 6.0f);
}
// v[0] = silu, v[1..8] = spline basis values
__device__ __forceinline__ void fill_slots(float x, float* v) {
    v[0] = siluf(x);
    int m; float n0, n1, n2, n3;
    spline_local(x, m, n0, n1, n2, n3);
    if (m >= 0 && m <= 10) {
        int j0 = m - 3;
        if (m >= 3)           v[1 + j0]     = n0;
        if (m >= 2 && m <= 9) v[1 + j0 + 1] = n1;
        if (m >= 1 && m <= 8) v[1 + j0 + 2] = n2;
        if (m <= 7)           v[1 + m]      = n3;
    }
}
__device__ __forceinline__ void cvt_pair(float v0, float v1, uint32_t& hi, uint32_t& lo) {
    __nv_bfloat16 h0 = __float2bfloat16_rn(v0), h1 = __float2bfloat16_rn(v1);
    float r0 = v0 - __bfloat162float(h0), r1 = v1 - __bfloat162float(h1);
    __nv_bfloat16 l0 = __float2bfloat16_rn(r0), l1 = __float2bfloat16_rn(r1);
    hi = ((uint32_t)__bfloat16_as_ushort(h1) << 16) | __bfloat16_as_ushort(h0);
    lo = ((uint32_t)__bfloat16_as_ushort(l1) << 16) | __bfloat16_as_ushort(l0);
}
__device__ __forceinline__ float fetch_x(int i, int rb,
                                         const float* __restrict__ hist,
                                         const float* __restrict__ statf,
                                         const float* __restrict__ timef,
                                         const float* __restrict__ emb, int sid) {
    if (i < 192) return hist[rb * 192 + i];
    if (i < 195) return statf[rb * 3 + (i - 192)];
    if (i < 203) return timef[rb * 8 + (i - 195)];
    return emb[sid * 16 + (i - 203)];
}

// ---------------- W repack: split hi/lo, chunked, padded rows ----------------
__global__ void repack_kernel(const float* __restrict__ wb1, const float* __restrict__ c1) {
    int idx = blockIdx.x * blockDim.x + threadIdx.x;
    if (idx >= KTOT * WS) return;
    int k = idx / WS, n = idx - (idx / WS) * WS;
    int chunk = k / CK, kl = k - chunk * CK;
    float val = 0.0f;
    if (n < HID) {
        if (kl < 16) {
            int i = chunk * 16 + kl;
            if (i < INDIM) val = wb1[i * HID + n];
        } else {
            int q = kl - 16;
            int i = chunk * 16 + (q >> 3), g = q & 7;
            if (i < INDIM) val = c1[(i * HID + n) * 8 + g];
        }
    }
    __nv_bfloat16 h = __float2bfloat16_rn(val);
    __nv_bfloat16 l = __float2bfloat16_rn(val - __bfloat162float(h));
    unsigned char* base = Wimg + (size_t)chunk * WCHUNK + kl * (WS * 2) + n * 2;
    *reinterpret_cast<__nv_bfloat16*>(base) = h;
    *reinterpret_cast<__nv_bfloat16*>(base + WCHUNK_HALF) = l;
}

// ---------------- main fused kernel ----------------
extern __shared__ __align__(16) unsigned char smem[];

__global__ __launch_bounds__(THREADS, 2)
void kan_main(const float* __restrict__ hist, const float* __restrict__ statf,
              const float* __restrict__ timef, const int* __restrict__ st_idx,
              const float* __restrict__ emb, const float* __restrict__ wb2,
              const float* __restrict__ c2, float* __restrict__ out) {
    const uint32_t sbase = smem_u32(smem);
    const int t = threadIdx.x;
    const int lane = t & 31;
    const int wid = t >> 5;
    const int wm = wid >> 1;         // m-warp: rows wm*32
    const int wn = wid & 1;          // n-warp: cols wn*32
    const int row0 = blockIdx.x * MROWS;
    int* sidx = reinterpret_cast<int*>(smem + SM_SIDX);

    if (t < MROWS) sidx[t] = st_idx[row0 + t];
    __syncthreads();

    float acc[2][4][4];
#pragma unroll
    for (int mt = 0; mt < 2; mt++)
#pragma unroll
        for (int nt = 0; nt < 4; nt++)
#pragma unroll
            for (int e = 0; e < 4; e++) acc[mt][nt][e] = 0.0f;

    const int brow = t & 63;         // build row
    const int bgrp = t >> 6;         // build input group (8 inputs)

    for (int c = 0; c < NCH; c++) {
        // ---- issue W chunk load (overlaps build) ----
        {
            const unsigned char* src = Wimg + (size_t)c * WCHUNK;
#pragma unroll
            for (int n = t; n < WCHUNK / 16; n += THREADS)
                cp16(sbase + SM_W + n * 16, src + n * 16);
            asm volatile("cp.async.commit_group;");
        }

        // ---- build A chunk: 8 cells per thread ----
        {
            int i0 = c * 16 + bgrp * 8;
            int rb = row0 + brow;
            float xv[8];
            if (i0 + 7 < 192) {
                float4 f0 = *reinterpret_cast<const float4*>(hist + (size_t)rb * 192 + i0);
                float4 f1 = *reinterpret_cast<const float4*>(hist + (size_t)rb * 192 + i0 + 4);
                xv[0] = f0.x; xv[1] = f0.y; xv[2] = f0.z; xv[3] = f0.w;
                xv[4] = f1.x; xv[5] = f1.y; xv[6] = f1.z; xv[7] = f1.w;
            } else {
                int sid = sidx[brow];
#pragma unroll
                for (int j = 0; j < 8; j++) {
                    int i = i0 + j;
                    xv[j] = (i < INDIM) ? fetch_x(i, rb, hist, statf, timef, emb, sid) : 0.0f;
                }
            }
            unsigned char* ah = smem + SM_A  + brow * (AS * 2);
            unsigned char* al = smem + SM_AL + brow * (AS * 2);
            float fb[8];
#pragma unroll
            for (int j = 0; j < 8; j++) {
                float v[9];
#pragma unroll
                for (int s = 0; s < 9; s++) v[s] = 0.0f;
                if (i0 + j < INDIM) fill_slots(xv[j], v);
                fb[j] = v[0];
                uint32_t h0, l0, h1, l1, h2, l2, h3, l3;
                cvt_pair(v[1], v[2], h0, l0);
                cvt_pair(v[3], v[4], h1, l1);
                cvt_pair(v[5], v[6], h2, l2);
                cvt_pair(v[7], v[8], h3, l3);
                int off = 32 + bgrp * 128 + j * 16;
                *reinterpret_cast<uint4*>(ah + off) = make_uint4(h0, h1, h2, h3);
                *reinterpret_cast<uint4*>(al + off) = make_uint4(l0, l1, l2, l3);
            }
            uint32_t h0, l0, h1, l1, h2, l2, h3, l3;
            cvt_pair(fb[0], fb[1], h0, l0);
            cvt_pair(fb[2], fb[3], h1, l1);
            cvt_pair(fb[4], fb[5], h2, l2);
            cvt_pair(fb[6], fb[7], h3, l3);
            *reinterpret_cast<uint4*>(ah + bgrp * 16) = make_uint4(h0, h1, h2, h3);
            *reinterpret_cast<uint4*>(al + bgrp * 16) = make_uint4(l0, l1, l2, l3);
        }

        asm volatile("cp.async.wait_group 0;");
        __syncthreads();

        // ---- MMA: 9 k16 steps ----
        const uint32_t aAh = sbase + SM_A, aAl = sbase + SM_AL, aW = sbase + SM_W;
        const int arow = wm * 32 + (lane & 15);
        const int acolh = (lane >> 4) * 8;
        const int bj = lane >> 3, bw = lane & 7;
#pragma unroll
        for (int ks = 0; ks < 9; ks++) {
            uint32_t ah[2][4], al_[2][4], bh[2][4], bl[2][4];
            int kcol = ks * 16 + acolh;
#pragma unroll
            for (int mt = 0; mt < 2; mt++) {
                uint32_t ad = ((arow + mt * 16) * AS + kcol) * 2;
                ldsm4(ah[mt],  aAh + ad);
                ldsm4(al_[mt], aAl + ad);
            }
            int kk = ks * 16 + (bj & 1) * 8 + bw;
#pragma unroll
            for (int nt = 0; nt < 2; nt++) {
                int n = wn * 32 + nt * 16 + (bj >> 1) * 8;
                uint32_t bd = kk * (WS * 2) + n * 2;
                ldsm4t(bh[nt], aW + bd);
                ldsm4t(bl[nt], aW + WCHUNK_HALF + bd);
            }
#pragma unroll
            for (int mt = 0; mt < 2; mt++)
#pragma unroll
                for (int nt = 0; nt < 4; nt++) {
                    uint32_t b0h = bh[nt >> 1][(nt & 1) * 2], b1h = bh[nt >> 1][(nt & 1) * 2 + 1];
                    uint32_t b0l = bl[nt >> 1][(nt & 1) * 2], b1l = bl[nt >> 1][(nt & 1) * 2 + 1];
                    mma16816(acc[mt][nt], ah[mt],  b0h, b1h);
                    mma16816(acc[mt][nt], ah[mt],  b0l, b1l);
                    mma16816(acc[mt][nt], al_[mt], b0h, b1h);
                }
        }
        __syncthreads();
    }

    // ---- write h to smem (reuse Ah region), then layer 2 ----
    float* h = reinterpret_cast<float*>(smem + SM_A);   // h[64][66]
#pragma unroll
    for (int mt = 0; mt < 2; mt++)
#pragma unroll
        for (int nt = 0; nt < 4; nt++) {
            int r0 = wm * 32 + mt * 16 + (lane >> 2);
            int col = wn * 32 + nt * 8 + (lane & 3) * 2;
            *reinterpret_cast<float2*>(&h[r0 * 66 + col]) =
                make_float2(acc[mt][nt][0], acc[mt][nt][1]);
            *reinterpret_cast<float2*>(&h[(r0 + 8) * 66 + col]) =
                make_float2(acc[mt][nt][2], acc[mt][nt][3]);
        }
    __syncthreads();

    {
        const int row = t >> 1;
        const int sub = t & 1;
        float accum = 0.0f;
#pragma unroll
        for (int kk = 0; kk < 32; kk++) {
            int o = sub + kk * 2;
            float xv = h[row * 66 + o];
            float v = siluf(xv) * __ldg(&wb2[o]);
            int m; float n0, n1, n2, n3;
            spline_local(xv, m, n0, n1, n2, n3);
            if (m >= 0 && m <= 10) {
                int j0 = m - 3;
                if (m >= 3)           v += n0 * __ldg(&c2[o * 8 + j0]);
                if (m >= 2 && m <= 9) v += n1 * __ldg(&c2[o * 8 + j0 + 1]);
                if (m >= 1 && m <= 8) v += n2 * __ldg(&c2[o * 8 + j0 + 2]);
                if (m <= 7)           v += n3 * __ldg(&c2[o * 8 + m]);
            }
            accum += v;
        }
        accum += __shfl_xor_sync(0xffffffffu, accum, 1);
        if (sub == 0) out[row0 + row] = accum;
    }
}

// ---------------- launch ----------------
extern "C" void kernel_launch(void* const* d_in, const int* in_sizes, int n_in,
                              void* d_out, int out_size) {
    const float* hist  = (const float*)d_in[0];
    const float* statf = (const float*)d_in[1];
    const float* timef = (const float*)d_in[2];
    const int*   sti   = (const int*)  d_in[3];
    const float* emb   = (const float*)d_in[4];
    const float* wb1   = (const float*)d_in[5];
    const float* c1    = (const float*)d_in[6];
    const float* wb2   = (const float*)d_in[7];
    const float* c2    = (const float*)d_in[8];
    float* out = (float*)d_out;

    static int configured = 0;
    if (!configured) {
        cudaFuncSetAttribute(kan_main, cudaFuncAttributeMaxDynamicSharedMemorySize,
                             SMEM_TOTAL);
        configured = 1;
    }
    repack_kernel<<<(KTOT * WS + 255) / 256, 256>>>(wb1, c1);
    kan_main<<<BATCH / MROWS, THREADS, SMEM_TOTAL>>>(hist, statf, timef, sti, emb,
                                                     wb2, c2, out);
}